// round 10
// baseline (speedup 1.0000x reference)
#include <cuda_runtime.h>
#include <cuda_fp16.h>
#include <math_constants.h>

// Problem constants (shapes fixed by the reference)
constexpr int NCH   = 32;     // n channels
constexpr int KNB   = 32;     // K neighbours
constexpr int MCL   = 16;     // M clusters
constexpr float MU_C = 1.0f;
constexpr int NMAX  = 131072; // scratch upper bound for N
constexpr int PB_BLOCKS = 296;   // 2 blocks/SM

// ---- device scratch (no allocations allowed) ----
static __device__ float   g_encpart[16 * NCH];            // per-chunk partial dots for encoded
static __device__ float   g_encoded[NCH];                 // encoded vector
static __device__ float   g_a[MCL * NCH];                 // a[m][i] = 1/(bw[i,m]*MU)^2
static __device__ __half2 g_dect2[(size_t)NMAX * (NCH/2)];// dec_t[p][i] = half(decoder[i][p]*encoded[i])
static __device__ float   g_Spart[PB_BLOCKS * NCH * KNB]; // per-block partial S, layout [block][k][i]
static __device__ float   g_invS[KNB * NCH];              // invS[k][i]

// ------------------------------------------------------------------
// Kernel A: partial dot products for encoded[i] = enc_w[i,:] . x
// float4 main loop; chunk boundaries are multiples of 4 elements.
// ------------------------------------------------------------------
__global__ void kA_encoded(const float* __restrict__ enc_w,
                           const float* __restrict__ x, int N) {
    int c = blockIdx.x;   // chunk
    int r = blockIdx.y;   // row (channel)
    int chunk = 4 * ((N + 63) / 64);      // 16 chunks of 4-aligned size
    int p0 = c * chunk;
    int p1 = min(p0 + chunk, N);

    const float* __restrict__ row = enc_w + (size_t)r * N;
    float s = 0.0f;
    int nv4 = (p1 - p0) / 4;              // p0 is 4-aligned
    const float4* __restrict__ row4 = reinterpret_cast<const float4*>(row + p0);
    const float4* __restrict__ x4   = reinterpret_cast<const float4*>(x + p0);
    for (int q = threadIdx.x; q < nv4; q += blockDim.x) {
        float4 a = row4[q], b = x4[q];
        s += a.x * b.x + a.y * b.y + a.z * b.z + a.w * b.w;
    }
    // scalar tail
    for (int p = p0 + 4 * nv4 + threadIdx.x; p < p1; p += blockDim.x)
        s += row[p] * x[p];

    #pragma unroll
    for (int o = 16; o > 0; o >>= 1)
        s += __shfl_xor_sync(0xffffffffu, s, o);

    __shared__ float ws[8];
    int lane = threadIdx.x & 31, wid = threadIdx.x >> 5;
    if (lane == 0) ws[wid] = s;
    __syncthreads();
    if (threadIdx.x == 0) {
        float t = 0.0f;
        #pragma unroll
        for (int w = 0; w < 8; w++) t += ws[w];
        g_encpart[c * NCH + r] = t;
    }
}

// ------------------------------------------------------------------
// Kernel B: reduce encoded partials, compute bandwidths -> a[m][i]
// ------------------------------------------------------------------
__global__ void kB_bandwidths(const float* __restrict__ bw_w,
                              const float* __restrict__ bw_b,
                              const float* __restrict__ enc_b) {
    __shared__ float enc_s[NCH];
    int t = threadIdx.x;
    if (t < NCH) {
        float s = enc_b[t];
        #pragma unroll
        for (int c = 0; c < 16; c++) s += g_encpart[c * NCH + t];
        enc_s[t] = s;
        g_encoded[t] = s;
    }
    __syncthreads();

    float s = bw_b[t];
    const float* __restrict__ wrow = bw_w + (size_t)t * NCH;
    #pragma unroll
    for (int q = 0; q < NCH; q++) s += wrow[q] * enc_s[q];
    float w = s * MU_C;
    int i = t / MCL, m = t % MCL;
    g_a[m * NCH + i] = 1.0f / (w * w);
}

// ------------------------------------------------------------------
// Kernel T: transposed + encoded-folded decoder, stored fp16
// ------------------------------------------------------------------
__global__ void kT_transpose(const float* __restrict__ decoder, int N) {
    __shared__ float enc_s[NCH];
    if (threadIdx.x < NCH) enc_s[threadIdx.x] = g_encoded[threadIdx.x];
    __syncthreads();

    int p = blockIdx.x * blockDim.x + threadIdx.x;
    if (p >= N) return;

    __half2 h[NCH / 2];
    #pragma unroll
    for (int q = 0; q < NCH / 2; q++) {
        float v0 = decoder[(size_t)(2 * q)     * N + p] * enc_s[2 * q];
        float v1 = decoder[(size_t)(2 * q + 1) * N + p] * enc_s[2 * q + 1];
        h[q] = __floats2half2_rn(v0, v1);
    }
    uint4* dst = reinterpret_cast<uint4*>(g_dect2 + (size_t)p * (NCH / 2));
    const uint4* src = reinterpret_cast<const uint4*>(h);
    #pragma unroll
    for (int q = 0; q < 4; q++) dst[q] = src[q];
}

// ------------------------------------------------------------------
// Kernel PB v3: S[i,k] = sum_j relu(1 - d[j,k]^2 * a[i, lab_j])
// warp processes 4 j's per stage; -d^2 staged in smem (LDS.64 serves 2 k's
// per MIO op, replacing 2 SHFLs). OOB j staged as -INF -> relu = 0.
// 296 blocks x 512 threads (2/SM).
// ------------------------------------------------------------------
__global__ void __launch_bounds__(512, 2) kPB_sums(
        const float* __restrict__ nd, const int* __restrict__ labels, int N) {
    __shared__ float a_s[MCL * NCH];
    __shared__ float S_sm[KNB * NCH];
    __shared__ float d2w[16][4][KNB];      // [warp][jj][k] = -d^2
    int t = threadIdx.x;
    if (t < MCL * NCH) a_s[t] = g_a[t];
    for (int u = t; u < KNB * NCH; u += 512) S_sm[u] = 0.0f;
    __syncthreads();

    int lane = t & 31, wid = t >> 5;       // 16 warps
    int gw = blockIdx.x * 16 + wid;
    int nwj = gridDim.x * 16 * 4;          // j stride (4 j per warp per stage)

    float acc[KNB];
    #pragma unroll
    for (int k = 0; k < KNB; k++) acc[k] = 0.0f;

    for (int jb = gw * 4; jb < N; jb += nwj) {
        float nd2v[4];
        int   labv[4];
        #pragma unroll
        for (int u = 0; u < 4; u++) {
            int j = jb + u;
            bool ok = (j < N);
            float dd = ok ? nd[(size_t)j * KNB + lane] : 0.0f;
            nd2v[u] = ok ? (-dd * dd) : -CUDART_INF_F;
            labv[u] = ok ? labels[j] : 0;
        }
        __syncwarp();                       // WAR: prior reads done
        #pragma unroll
        for (int u = 0; u < 4; u++) d2w[wid][u][lane] = nd2v[u];
        __syncwarp();                       // RAW: stores visible

        #pragma unroll
        for (int u = 0; u < 4; u++) {
            float a = a_s[labv[u] * NCH + lane];   // lane = channel i
            #pragma unroll
            for (int kp = 0; kp < KNB / 2; kp++) {
                float2 q = *reinterpret_cast<const float2*>(&d2w[wid][u][2 * kp]);
                float t0 = fmaf(q.x, a, 1.0f);
                float t1 = fmaf(q.y, a, 1.0f);
                acc[2 * kp]     += fmaxf(t0, 0.0f);
                acc[2 * kp + 1] += fmaxf(t1, 0.0f);
            }
        }
    }

    #pragma unroll
    for (int k = 0; k < KNB; k++)
        atomicAdd(&S_sm[k * NCH + lane], acc[k]);
    __syncthreads();

    for (int u = t; u < KNB * NCH; u += 512)
        g_Spart[blockIdx.x * (KNB * NCH) + u] = S_sm[u];
}

// ------------------------------------------------------------------
// Kernel PF: finalize invS[k][i] = 1 / sum_b Spart[b][k][i]
// ------------------------------------------------------------------
__global__ void kPF_finalize(int nblocks) {
    int u = blockIdx.x * 128 + threadIdx.x;
    float s0 = 0.0f, s1 = 0.0f, s2 = 0.0f, s3 = 0.0f;
    int b = 0;
    for (; b + 3 < nblocks; b += 4) {
        s0 += g_Spart[(b + 0) * (KNB * NCH) + u];
        s1 += g_Spart[(b + 1) * (KNB * NCH) + u];
        s2 += g_Spart[(b + 2) * (KNB * NCH) + u];
        s3 += g_Spart[(b + 3) * (KNB * NCH) + u];
    }
    for (; b < nblocks; b++) s0 += g_Spart[b * (KNB * NCH) + u];
    g_invS[u] = 1.0f / (s0 + s1 + s2 + s3);
}

// ------------------------------------------------------------------
// Kernel PC v3: out[j] = sum_k sum_i dec_t[id_jk][i] * win * invS[k][i]
// warp = 2 points (half-warp each), lane = channel PAIR.
// Software pipeline: next kp's d2/id LDS + both dect gathers issued
// BEFORE computing current kp -> LDG latency overlapped with compute.
// ------------------------------------------------------------------
__global__ void __launch_bounds__(512, 2) kPC_output(
        const float2* __restrict__ nd2, const int2* __restrict__ nid2,
        const int* __restrict__ labels, float* __restrict__ out, int N) {
    __shared__ float a_s[MCL][NCH];           // [lab][ch], pairs contiguous
    __shared__ float ivs4[16][16][4];         // [kp][sub][{(k0,i0),(k0,i1),(k1,i0),(k1,i1)}]
    __shared__ float d2_sm[16][16][2][2];     // [wid][kp][hw][2]
    __shared__ int   id_sm[16][16][2][2];     // [wid][kp][hw][2]

    int t = threadIdx.x;
    for (int u = t; u < MCL * NCH; u += 512)
        a_s[u / NCH][u % NCH] = g_a[u];
    for (int u = t; u < 16 * 16 * 4; u += 512) {
        int kp = u >> 6, sub = (u >> 2) & 15, q = u & 3;
        int k = 2 * kp + (q >> 1), i = 2 * sub + (q & 1);
        ivs4[kp][sub][q] = g_invS[k * NCH + i];
    }
    __syncthreads();

    int lane = t & 31, wid = t >> 5;         // 16 warps
    int hw   = lane >> 4;                    // which half-warp (which j)
    int sub  = lane & 15;                    // channel pair index

    int P  = (N + 1) >> 1;                   // number of j-pairs
    int nw = gridDim.x * 16;

    for (int p = blockIdx.x * 16 + wid; p < P; p += nw) {
        int jA = 2 * p;
        int jB = jA + 1;
        int jm = hw ? min(jB, N - 1) : jA;   // my point

        // load this point's d and id vectors (coalesced 128B per half-warp)
        float2 dp = nd2[(size_t)jm * 16 + sub];
        int2   ip = nid2[(size_t)jm * 16 + sub];
        float d2lo = dp.x * dp.x, d2hi = dp.y * dp.y;

        __syncwarp();
        *reinterpret_cast<float2*>(&d2_sm[wid][sub][hw][0]) = make_float2(d2lo, d2hi);
        *reinterpret_cast<int2*>(&id_sm[wid][sub][hw][0])   = ip;
        __syncwarp();

        int lab = labels[jm];
        float2 a01 = *reinterpret_cast<const float2*>(&a_s[lab][2 * sub]);

        // ---- pipeline prologue: stage kp = 0 ----
        float2 d2c = *reinterpret_cast<const float2*>(&d2_sm[wid][0][hw][0]);
        int2   idc = *reinterpret_cast<const int2*>(&id_sm[wid][0][hw][0]);
        __half2 vh0 = g_dect2[(size_t)idc.x * 16 + sub];
        __half2 vh1 = g_dect2[(size_t)idc.y * 16 + sub];

        float acc0 = 0.0f, acc1 = 0.0f;
        #pragma unroll
        for (int kp = 0; kp < 16; kp++) {
            // ---- issue next iteration's loads first ----
            int kn = (kp + 1) & 15;
            float2 d2n = *reinterpret_cast<const float2*>(&d2_sm[wid][kn][hw][0]);
            int2   idn = *reinterpret_cast<const int2*>(&id_sm[wid][kn][hw][0]);
            __half2 nvh0 = g_dect2[(size_t)idn.x * 16 + sub];
            __half2 nvh1 = g_dect2[(size_t)idn.y * 16 + sub];

            float4 iv = *reinterpret_cast<const float4*>(&ivs4[kp][sub][0]);

            float w00 = fmaxf(fmaf(-d2c.x, a01.x, 1.0f), 0.0f);
            float w01 = fmaxf(fmaf(-d2c.x, a01.y, 1.0f), 0.0f);
            float w10 = fmaxf(fmaf(-d2c.y, a01.x, 1.0f), 0.0f);
            float w11 = fmaxf(fmaf(-d2c.y, a01.y, 1.0f), 0.0f);

            float2 v0 = __half22float2(vh0);
            float2 v1 = __half22float2(vh1);

            acc0 = fmaf(v0.x * w00, iv.x, acc0);
            acc1 = fmaf(v0.y * w01, iv.y, acc1);
            acc0 = fmaf(v1.x * w10, iv.z, acc0);
            acc1 = fmaf(v1.y * w11, iv.w, acc1);

            d2c = d2n; vh0 = nvh0; vh1 = nvh1;
        }

        float s = acc0 + acc1;
        #pragma unroll
        for (int o = 1; o < 16; o <<= 1)
            s += __shfl_xor_sync(0xffffffffu, s, o);

        int jout = hw ? jB : jA;
        if (sub == 0 && jout < N) out[jout] = s;
    }
}

// ------------------------------------------------------------------
extern "C" void kernel_launch(void* const* d_in, const int* in_sizes, int n_in,
                              void* d_out, int out_size) {
    const float* x       = (const float*)d_in[0];
    const float* enc_w   = (const float*)d_in[1];
    const float* enc_b   = (const float*)d_in[2];
    const float* decoder = (const float*)d_in[3];
    const float* bw_w    = (const float*)d_in[4];
    const float* bw_b    = (const float*)d_in[5];
    const float* nd      = (const float*)d_in[6];
    const int*   nid     = (const int*)d_in[7];
    const int*   labels  = (const int*)d_in[8];
    float* out = (float*)d_out;
    int N = in_sizes[0];

    kA_encoded<<<dim3(16, NCH), 256>>>(enc_w, x, N);
    kB_bandwidths<<<1, NCH * MCL>>>(bw_w, bw_b, enc_b);
    kT_transpose<<<(N + 255) / 256, 256>>>(decoder, N);
    kPB_sums<<<PB_BLOCKS, 512>>>(nd, labels, N);
    kPF_finalize<<<8, 128>>>(PB_BLOCKS);
    kPC_output<<<296, 512>>>((const float2*)nd, (const int2*)nid, labels, out, N);
}

// round 11
// speedup vs baseline: 1.0449x; 1.0449x over previous
#include <cuda_runtime.h>
#include <cuda_fp16.h>
#include <math_constants.h>

// Problem constants (shapes fixed by the reference)
constexpr int NCH   = 32;     // n channels
constexpr int KNB   = 32;     // K neighbours
constexpr int MCL   = 16;     // M clusters
constexpr float MU_C = 1.0f;
constexpr int NMAX  = 131072; // scratch upper bound for N
constexpr int PB_BLOCKS = 296;   // 2 blocks/SM

// ---- device scratch (no allocations allowed) ----
static __device__ float   g_encpart[16 * NCH];            // per-chunk partial dots for encoded
static __device__ float   g_encoded[NCH];                 // encoded vector
static __device__ float   g_a[MCL * NCH];                 // a[m][i] = 1/(bw[i,m]*MU)^2
static __device__ __half2 g_dect2[(size_t)NMAX * (NCH/2)];// dec_t[p][i] = half(decoder[i][p]*encoded[i])
static __device__ float   g_Spart[PB_BLOCKS * NCH * KNB]; // per-block partial S, layout [block][k][i]
static __device__ float   g_invS[KNB * NCH];              // invS[k][i]

// ------------------------------------------------------------------
// Kernel A: partial dot products for encoded[i] = enc_w[i,:] . x
// ------------------------------------------------------------------
__global__ void kA_encoded(const float* __restrict__ enc_w,
                           const float* __restrict__ x, int N) {
    int c = blockIdx.x;   // chunk
    int r = blockIdx.y;   // row (channel)
    int chunk = 4 * ((N + 63) / 64);      // 16 chunks of 4-aligned size
    int p0 = c * chunk;
    int p1 = min(p0 + chunk, N);

    const float* __restrict__ row = enc_w + (size_t)r * N;
    float s = 0.0f;
    int nv4 = (p1 - p0) / 4;              // p0 is 4-aligned
    const float4* __restrict__ row4 = reinterpret_cast<const float4*>(row + p0);
    const float4* __restrict__ x4   = reinterpret_cast<const float4*>(x + p0);
    for (int q = threadIdx.x; q < nv4; q += blockDim.x) {
        float4 a = row4[q], b = x4[q];
        s += a.x * b.x + a.y * b.y + a.z * b.z + a.w * b.w;
    }
    for (int p = p0 + 4 * nv4 + threadIdx.x; p < p1; p += blockDim.x)
        s += row[p] * x[p];

    #pragma unroll
    for (int o = 16; o > 0; o >>= 1)
        s += __shfl_xor_sync(0xffffffffu, s, o);

    __shared__ float ws[8];
    int lane = threadIdx.x & 31, wid = threadIdx.x >> 5;
    if (lane == 0) ws[wid] = s;
    __syncthreads();
    if (threadIdx.x == 0) {
        float t = 0.0f;
        #pragma unroll
        for (int w = 0; w < 8; w++) t += ws[w];
        g_encpart[c * NCH + r] = t;
    }
}

// ------------------------------------------------------------------
// Kernel B: reduce encoded partials, compute bandwidths -> a[m][i]
// ------------------------------------------------------------------
__global__ void kB_bandwidths(const float* __restrict__ bw_w,
                              const float* __restrict__ bw_b,
                              const float* __restrict__ enc_b) {
    __shared__ float enc_s[NCH];
    int t = threadIdx.x;
    if (t < NCH) {
        float s = enc_b[t];
        #pragma unroll
        for (int c = 0; c < 16; c++) s += g_encpart[c * NCH + t];
        enc_s[t] = s;
        g_encoded[t] = s;
    }
    __syncthreads();

    float s = bw_b[t];
    const float* __restrict__ wrow = bw_w + (size_t)t * NCH;
    #pragma unroll
    for (int q = 0; q < NCH; q++) s += wrow[q] * enc_s[q];
    float w = s * MU_C;
    int i = t / MCL, m = t % MCL;
    g_a[m * NCH + i] = 1.0f / (w * w);
}

// ------------------------------------------------------------------
// Kernel T: transposed + encoded-folded decoder, stored fp16
// ------------------------------------------------------------------
__global__ void kT_transpose(const float* __restrict__ decoder, int N) {
    __shared__ float enc_s[NCH];
    if (threadIdx.x < NCH) enc_s[threadIdx.x] = g_encoded[threadIdx.x];
    __syncthreads();

    int p = blockIdx.x * blockDim.x + threadIdx.x;
    if (p >= N) return;

    __half2 h[NCH / 2];
    #pragma unroll
    for (int q = 0; q < NCH / 2; q++) {
        float v0 = decoder[(size_t)(2 * q)     * N + p] * enc_s[2 * q];
        float v1 = decoder[(size_t)(2 * q + 1) * N + p] * enc_s[2 * q + 1];
        h[q] = __floats2half2_rn(v0, v1);
    }
    uint4* dst = reinterpret_cast<uint4*>(g_dect2 + (size_t)p * (NCH / 2));
    const uint4* src = reinterpret_cast<const uint4*>(h);
    #pragma unroll
    for (int q = 0; q < 4; q++) dst[q] = src[q];
}

// ------------------------------------------------------------------
// Kernel PB v4: S[i,k] = sum_j relu(1 - d[j,k]^2 * a[i, lab_j])
// warp processes 4 j's per stage; -d^2 staged in smem; LDS.128 serves
// 4 k's per MIO op. OOB j staged as -INF -> relu = 0.
// ------------------------------------------------------------------
__global__ void __launch_bounds__(512, 2) kPB_sums(
        const float* __restrict__ nd, const int* __restrict__ labels, int N) {
    __shared__ float a_s[MCL * NCH];
    __shared__ float S_sm[KNB * NCH];
    __shared__ __align__(16) float d2w[16][4][KNB];   // [warp][jj][k] = -d^2
    int t = threadIdx.x;
    if (t < MCL * NCH) a_s[t] = g_a[t];
    for (int u = t; u < KNB * NCH; u += 512) S_sm[u] = 0.0f;
    __syncthreads();

    int lane = t & 31, wid = t >> 5;       // 16 warps
    int gw = blockIdx.x * 16 + wid;
    int nwj = gridDim.x * 16 * 4;          // j stride (4 j per warp per stage)

    float acc[KNB];
    #pragma unroll
    for (int k = 0; k < KNB; k++) acc[k] = 0.0f;

    for (int jb = gw * 4; jb < N; jb += nwj) {
        float nd2v[4];
        int   labv[4];
        #pragma unroll
        for (int u = 0; u < 4; u++) {
            int j = jb + u;
            bool ok = (j < N);
            float dd = ok ? nd[(size_t)j * KNB + lane] : 0.0f;
            nd2v[u] = ok ? (-dd * dd) : -CUDART_INF_F;
            labv[u] = ok ? labels[j] : 0;
        }
        __syncwarp();                       // WAR: prior reads done
        #pragma unroll
        for (int u = 0; u < 4; u++) d2w[wid][u][lane] = nd2v[u];
        __syncwarp();                       // RAW: stores visible

        #pragma unroll
        for (int u = 0; u < 4; u++) {
            float a = a_s[labv[u] * NCH + lane];   // lane = channel i
            #pragma unroll
            for (int kq = 0; kq < KNB / 4; kq++) {
                float4 q = *reinterpret_cast<const float4*>(&d2w[wid][u][4 * kq]);
                acc[4 * kq]     += fmaxf(fmaf(q.x, a, 1.0f), 0.0f);
                acc[4 * kq + 1] += fmaxf(fmaf(q.y, a, 1.0f), 0.0f);
                acc[4 * kq + 2] += fmaxf(fmaf(q.z, a, 1.0f), 0.0f);
                acc[4 * kq + 3] += fmaxf(fmaf(q.w, a, 1.0f), 0.0f);
            }
        }
    }

    #pragma unroll
    for (int k = 0; k < KNB; k++)
        atomicAdd(&S_sm[k * NCH + lane], acc[k]);
    __syncthreads();

    for (int u = t; u < KNB * NCH; u += 512)
        g_Spart[blockIdx.x * (KNB * NCH) + u] = S_sm[u];
}

// ------------------------------------------------------------------
// Kernel PF: finalize invS[k][i] = 1 / sum_b Spart[b][k][i]
// ------------------------------------------------------------------
__global__ void kPF_finalize(int nblocks) {
    int u = blockIdx.x * 128 + threadIdx.x;
    float s0 = 0.0f, s1 = 0.0f, s2 = 0.0f, s3 = 0.0f;
    int b = 0;
    for (; b + 3 < nblocks; b += 4) {
        s0 += g_Spart[(b + 0) * (KNB * NCH) + u];
        s1 += g_Spart[(b + 1) * (KNB * NCH) + u];
        s2 += g_Spart[(b + 2) * (KNB * NCH) + u];
        s3 += g_Spart[(b + 3) * (KNB * NCH) + u];
    }
    for (; b < nblocks; b++) s0 += g_Spart[b * (KNB * NCH) + u];
    g_invS[u] = 1.0f / (s0 + s1 + s2 + s3);
}

// ------------------------------------------------------------------
// Kernel PC v4: out[j] = sum_k sum_i dec_t[id_jk][i] * win * invS[k][i]
// warp = 2 points (half-warp each), lane = channel PAIR.
// 2-DEEP gather pipeline: gather for kp issued at iteration kp-2 ->
// ~2 iterations (>500 cyc with 8 warps/SMSP) of coverage vs ~250 cyc L2.
// 32-bit gather indexing (g_dect2 = 6.4MB).
// ------------------------------------------------------------------
__global__ void __launch_bounds__(512, 2) kPC_output(
        const float2* __restrict__ nd2, const int2* __restrict__ nid2,
        const int* __restrict__ labels, float* __restrict__ out, int N) {
    __shared__ __align__(16) float a_s[MCL][NCH];     // [lab][ch], pairs contiguous
    __shared__ __align__(16) float ivs4[16][16][4];   // [kp][sub][{(k0,i0),(k0,i1),(k1,i0),(k1,i1)}]
    __shared__ __align__(16) float d2_sm[16][16][2][2]; // [wid][kp][hw][2]
    __shared__ __align__(16) int   id_sm[16][16][2][2]; // [wid][kp][hw][2]

    int t = threadIdx.x;
    for (int u = t; u < MCL * NCH; u += 512)
        a_s[u / NCH][u % NCH] = g_a[u];
    for (int u = t; u < 16 * 16 * 4; u += 512) {
        int kp = u >> 6, sub = (u >> 2) & 15, q = u & 3;
        int k = 2 * kp + (q >> 1), i = 2 * sub + (q & 1);
        ivs4[kp][sub][q] = g_invS[k * NCH + i];
    }
    __syncthreads();

    int lane = t & 31, wid = t >> 5;         // 16 warps
    int hw   = lane >> 4;                    // which half-warp (which j)
    int sub  = lane & 15;                    // channel pair index

    const __half2* __restrict__ gb = g_dect2 + sub;   // per-thread gather base

    int P  = (N + 1) >> 1;                   // number of j-pairs
    int nw = gridDim.x * 16;

    for (int p = blockIdx.x * 16 + wid; p < P; p += nw) {
        int jA = 2 * p;
        int jB = jA + 1;
        int jm = hw ? min(jB, N - 1) : jA;   // my point

        // load this point's d and id vectors (coalesced 128B per half-warp)
        float2 dp = nd2[(size_t)jm * 16 + sub];
        int2   ip = nid2[(size_t)jm * 16 + sub];
        float d2lo = dp.x * dp.x, d2hi = dp.y * dp.y;

        __syncwarp();
        *reinterpret_cast<float2*>(&d2_sm[wid][sub][hw][0]) = make_float2(d2lo, d2hi);
        *reinterpret_cast<int2*>(&id_sm[wid][sub][hw][0])   = ip;
        __syncwarp();

        int lab = labels[jm];
        float2 a01 = *reinterpret_cast<const float2*>(&a_s[lab][2 * sub]);

        // ---- pipeline prologue: issue gathers for kp = 0 and kp = 1 ----
        __half2 vh[2][2];
        {
            int2 id0 = *reinterpret_cast<const int2*>(&id_sm[wid][0][hw][0]);
            int2 id1 = *reinterpret_cast<const int2*>(&id_sm[wid][1][hw][0]);
            vh[0][0] = gb[(unsigned)id0.x * 16u];
            vh[0][1] = gb[(unsigned)id0.y * 16u];
            vh[1][0] = gb[(unsigned)id1.x * 16u];
            vh[1][1] = gb[(unsigned)id1.y * 16u];
        }

        float acc0 = 0.0f, acc1 = 0.0f;
        #pragma unroll
        for (int kp = 0; kp < 16; kp++) {
            // consume current slot (this is the wait point for the kp gather)
            float2 v0 = __half22float2(vh[kp & 1][0]);
            float2 v1 = __half22float2(vh[kp & 1][1]);

            // immediately re-issue the freed slot for kp+2
            if (kp + 2 < 16) {
                int2 idn = *reinterpret_cast<const int2*>(&id_sm[wid][kp + 2][hw][0]);
                vh[kp & 1][0] = gb[(unsigned)idn.x * 16u];
                vh[kp & 1][1] = gb[(unsigned)idn.y * 16u];
            }

            float2 d2c = *reinterpret_cast<const float2*>(&d2_sm[wid][kp][hw][0]);
            float4 iv  = *reinterpret_cast<const float4*>(&ivs4[kp][sub][0]);

            float w00 = fmaxf(fmaf(-d2c.x, a01.x, 1.0f), 0.0f);
            float w01 = fmaxf(fmaf(-d2c.x, a01.y, 1.0f), 0.0f);
            float w10 = fmaxf(fmaf(-d2c.y, a01.x, 1.0f), 0.0f);
            float w11 = fmaxf(fmaf(-d2c.y, a01.y, 1.0f), 0.0f);

            acc0 = fmaf(v0.x * w00, iv.x, acc0);
            acc1 = fmaf(v0.y * w01, iv.y, acc1);
            acc0 = fmaf(v1.x * w10, iv.z, acc0);
            acc1 = fmaf(v1.y * w11, iv.w, acc1);
        }

        float s = acc0 + acc1;
        #pragma unroll
        for (int o = 1; o < 16; o <<= 1)
            s += __shfl_xor_sync(0xffffffffu, s, o);

        int jout = hw ? jB : jA;
        if (sub == 0 && jout < N) out[jout] = s;
    }
}

// ------------------------------------------------------------------
extern "C" void kernel_launch(void* const* d_in, const int* in_sizes, int n_in,
                              void* d_out, int out_size) {
    const float* x       = (const float*)d_in[0];
    const float* enc_w   = (const float*)d_in[1];
    const float* enc_b   = (const float*)d_in[2];
    const float* decoder = (const float*)d_in[3];
    const float* bw_w    = (const float*)d_in[4];
    const float* bw_b    = (const float*)d_in[5];
    const float* nd      = (const float*)d_in[6];
    const int*   nid     = (const int*)d_in[7];
    const int*   labels  = (const int*)d_in[8];
    float* out = (float*)d_out;
    int N = in_sizes[0];

    kA_encoded<<<dim3(16, NCH), 256>>>(enc_w, x, N);
    kB_bandwidths<<<1, NCH * MCL>>>(bw_w, bw_b, enc_b);
    kT_transpose<<<(N + 255) / 256, 256>>>(decoder, N);
    kPB_sums<<<PB_BLOCKS, 512>>>(nd, labels, N);
    kPF_finalize<<<8, 128>>>(PB_BLOCKS);
    kPC_output<<<296, 512>>>((const float2*)nd, (const int2*)nid, labels, out, N);
}

// round 12
// speedup vs baseline: 1.1321x; 1.0835x over previous
#include <cuda_runtime.h>
#include <cuda_fp16.h>
#include <math_constants.h>

// Problem constants (shapes fixed by the reference)
constexpr int NCH   = 32;     // n channels
constexpr int KNB   = 32;     // K neighbours
constexpr int MCL   = 16;     // M clusters
constexpr float MU_C = 1.0f;
constexpr int NMAX  = 131072; // scratch upper bound for N
constexpr int PB_BLOCKS = 296;   // 2 blocks/SM

// ---- device scratch (no allocations allowed) ----
static __device__ float   g_encpart[16 * NCH];            // per-chunk partial dots for encoded
static __device__ float   g_encoded[NCH];                 // encoded vector
static __device__ float   g_a[MCL * NCH];                 // a[m][i] = 1/(bw[i,m]*MU)^2
static __device__ __half2 g_dect2[(size_t)NMAX * (NCH/2)];// dec_t[p][i] = half(decoder[i][p]*encoded[i])
static __device__ float   g_Spart[PB_BLOCKS * NCH * KNB]; // per-block partial S, layout [block][k][i]
static __device__ float   g_invS[KNB * NCH];              // invS[k][i]

// ------------------------------------------------------------------
// Kernel A: partial dot products for encoded[i] = enc_w[i,:] . x
// ------------------------------------------------------------------
__global__ void kA_encoded(const float* __restrict__ enc_w,
                           const float* __restrict__ x, int N) {
    int c = blockIdx.x;   // chunk
    int r = blockIdx.y;   // row (channel)
    int chunk = 4 * ((N + 63) / 64);      // 16 chunks of 4-aligned size
    int p0 = c * chunk;
    int p1 = min(p0 + chunk, N);

    const float* __restrict__ row = enc_w + (size_t)r * N;
    float s = 0.0f;
    int nv4 = (p1 - p0) / 4;              // p0 is 4-aligned
    const float4* __restrict__ row4 = reinterpret_cast<const float4*>(row + p0);
    const float4* __restrict__ x4   = reinterpret_cast<const float4*>(x + p0);
    for (int q = threadIdx.x; q < nv4; q += blockDim.x) {
        float4 a = row4[q], b = x4[q];
        s += a.x * b.x + a.y * b.y + a.z * b.z + a.w * b.w;
    }
    for (int p = p0 + 4 * nv4 + threadIdx.x; p < p1; p += blockDim.x)
        s += row[p] * x[p];

    #pragma unroll
    for (int o = 16; o > 0; o >>= 1)
        s += __shfl_xor_sync(0xffffffffu, s, o);

    __shared__ float ws[8];
    int lane = threadIdx.x & 31, wid = threadIdx.x >> 5;
    if (lane == 0) ws[wid] = s;
    __syncthreads();
    if (threadIdx.x == 0) {
        float t = 0.0f;
        #pragma unroll
        for (int w = 0; w < 8; w++) t += ws[w];
        g_encpart[c * NCH + r] = t;
    }
}

// ------------------------------------------------------------------
// Kernel B: reduce encoded partials, compute bandwidths -> a[m][i]
// ------------------------------------------------------------------
__global__ void kB_bandwidths(const float* __restrict__ bw_w,
                              const float* __restrict__ bw_b,
                              const float* __restrict__ enc_b) {
    __shared__ float enc_s[NCH];
    int t = threadIdx.x;
    if (t < NCH) {
        float s = enc_b[t];
        #pragma unroll
        for (int c = 0; c < 16; c++) s += g_encpart[c * NCH + t];
        enc_s[t] = s;
        g_encoded[t] = s;
    }
    __syncthreads();

    float s = bw_b[t];
    const float* __restrict__ wrow = bw_w + (size_t)t * NCH;
    #pragma unroll
    for (int q = 0; q < NCH; q++) s += wrow[q] * enc_s[q];
    float w = s * MU_C;
    int i = t / MCL, m = t % MCL;
    g_a[m * NCH + i] = 1.0f / (w * w);
}

// ------------------------------------------------------------------
// Kernel T: transposed + encoded-folded decoder, stored fp16
// ------------------------------------------------------------------
__global__ void kT_transpose(const float* __restrict__ decoder, int N) {
    __shared__ float enc_s[NCH];
    if (threadIdx.x < NCH) enc_s[threadIdx.x] = g_encoded[threadIdx.x];
    __syncthreads();

    int p = blockIdx.x * blockDim.x + threadIdx.x;
    if (p >= N) return;

    __half2 h[NCH / 2];
    #pragma unroll
    for (int q = 0; q < NCH / 2; q++) {
        float v0 = decoder[(size_t)(2 * q)     * N + p] * enc_s[2 * q];
        float v1 = decoder[(size_t)(2 * q + 1) * N + p] * enc_s[2 * q + 1];
        h[q] = __floats2half2_rn(v0, v1);
    }
    uint4* dst = reinterpret_cast<uint4*>(g_dect2 + (size_t)p * (NCH / 2));
    const uint4* src = reinterpret_cast<const uint4*>(h);
    #pragma unroll
    for (int q = 0; q < 4; q++) dst[q] = src[q];
}

// ------------------------------------------------------------------
// Kernel PB v5: S[i,k] = sum_j relu(1 - d[j,k]^2 * a[i, lab_j])
// Packed fma.rn.f32x2 window math: per 4 k's: 1 LDS(v2.u64) + 2 FFMA2
// + 4 FMNMX + 4 FADD. -d^2 staged in smem; OOB j staged as -INF.
// ------------------------------------------------------------------
__global__ void __launch_bounds__(512, 2) kPB_sums(
        const float* __restrict__ nd, const int* __restrict__ labels, int N) {
    __shared__ float a_s[MCL * NCH];
    __shared__ float S_sm[KNB * NCH];
    __shared__ __align__(16) float d2w[16][4][KNB];   // [warp][jj][k] = -d^2
    int t = threadIdx.x;
    if (t < MCL * NCH) a_s[t] = g_a[t];
    for (int u = t; u < KNB * NCH; u += 512) S_sm[u] = 0.0f;
    __syncthreads();

    int lane = t & 31, wid = t >> 5;       // 16 warps
    int gw = blockIdx.x * 16 + wid;
    int nwj = gridDim.x * 16 * 4;          // j stride (4 j per warp per stage)

    unsigned long long one2;
    asm("mov.b64 %0, {%1, %1};" : "=l"(one2) : "f"(1.0f));

    float acc[KNB];
    #pragma unroll
    for (int k = 0; k < KNB; k++) acc[k] = 0.0f;

    for (int jb = gw * 4; jb < N; jb += nwj) {
        float nd2v[4];
        int   labv[4];
        #pragma unroll
        for (int u = 0; u < 4; u++) {
            int j = jb + u;
            bool ok = (j < N);
            float dd = ok ? nd[(size_t)j * KNB + lane] : 0.0f;
            nd2v[u] = ok ? (-dd * dd) : -CUDART_INF_F;
            labv[u] = ok ? labels[j] : 0;
        }
        __syncwarp();                       // WAR: prior reads done
        #pragma unroll
        for (int u = 0; u < 4; u++) d2w[wid][u][lane] = nd2v[u];
        __syncwarp();                       // RAW: stores visible

        #pragma unroll
        for (int u = 0; u < 4; u++) {
            float a = a_s[labv[u] * NCH + lane];   // lane = channel i
            unsigned long long a2;
            asm("mov.b64 %0, {%1, %1};" : "=l"(a2) : "f"(a));
            unsigned sbase = (unsigned)__cvta_generic_to_shared(&d2w[wid][u][0]);
            #pragma unroll
            for (int kq = 0; kq < KNB / 4; kq++) {
                unsigned long long q0, q1, w0, w1;
                asm volatile("ld.shared.v2.u64 {%0, %1}, [%2];"
                             : "=l"(q0), "=l"(q1) : "r"(sbase + 16u * kq));
                asm("fma.rn.f32x2 %0, %1, %2, %3;" : "=l"(w0) : "l"(q0), "l"(a2), "l"(one2));
                asm("fma.rn.f32x2 %0, %1, %2, %3;" : "=l"(w1) : "l"(q1), "l"(a2), "l"(one2));
                float f0, f1, f2, f3;
                asm("mov.b64 {%0, %1}, %2;" : "=f"(f0), "=f"(f1) : "l"(w0));
                asm("mov.b64 {%0, %1}, %2;" : "=f"(f2), "=f"(f3) : "l"(w1));
                acc[4 * kq + 0] += fmaxf(f0, 0.0f);
                acc[4 * kq + 1] += fmaxf(f1, 0.0f);
                acc[4 * kq + 2] += fmaxf(f2, 0.0f);
                acc[4 * kq + 3] += fmaxf(f3, 0.0f);
            }
        }
    }

    #pragma unroll
    for (int k = 0; k < KNB; k++)
        atomicAdd(&S_sm[k * NCH + lane], acc[k]);
    __syncthreads();

    for (int u = t; u < KNB * NCH; u += 512)
        g_Spart[blockIdx.x * (KNB * NCH) + u] = S_sm[u];
}

// ------------------------------------------------------------------
// Kernel PF: finalize invS[k][i] = 1 / sum_b Spart[b][k][i]
// ------------------------------------------------------------------
__global__ void kPF_finalize(int nblocks) {
    int u = blockIdx.x * 128 + threadIdx.x;
    float s0 = 0.0f, s1 = 0.0f, s2 = 0.0f, s3 = 0.0f;
    int b = 0;
    for (; b + 3 < nblocks; b += 4) {
        s0 += g_Spart[(b + 0) * (KNB * NCH) + u];
        s1 += g_Spart[(b + 1) * (KNB * NCH) + u];
        s2 += g_Spart[(b + 2) * (KNB * NCH) + u];
        s3 += g_Spart[(b + 3) * (KNB * NCH) + u];
    }
    for (; b < nblocks; b++) s0 += g_Spart[b * (KNB * NCH) + u];
    g_invS[u] = 1.0f / (s0 + s1 + s2 + s3);
}

// ------------------------------------------------------------------
// Kernel PC v5: out[j] = sum_k sum_i dec_t[id_jk][i] * win * invS[k][i]
// warp = 4 points (8 lanes each), lane = channel QUAD (4 ch).
// Gathers are LDG.64: one instr fetches a 64B decoder row per 8-lane
// group x4 groups. 2-slot gather ring over k-pairs. 32-bit indexing.
// ------------------------------------------------------------------
__global__ void __launch_bounds__(512, 2) kPC_output(
        const float4* __restrict__ nd4, const int4* __restrict__ nid4,
        const int* __restrict__ labels, float* __restrict__ out, int N) {
    __shared__ __align__(16) float a_s[MCL][NCH];      // [lab][ch]
    __shared__ __align__(16) float ivs_s[KNB][8][4];   // [k][chquad][4]
    __shared__ __align__(16) float d2_sm[16][4][KNB];  // [wid][jj][k] = d^2
    __shared__ __align__(16) int   id_sm[16][4][KNB];  // [wid][jj][k]

    int t = threadIdx.x;
    for (int u = t; u < MCL * NCH; u += 512)
        a_s[u / NCH][u % NCH] = g_a[u];
    for (int u = t; u < KNB * NCH; u += 512) {
        int k = u / NCH, i = u % NCH;
        ivs_s[k][i >> 2][i & 3] = g_invS[u];
    }
    __syncthreads();

    int lane = t & 31, wid = t >> 5;     // 16 warps
    int jj   = lane >> 3;                // which of 4 points
    int sub  = lane & 7;                 // channel quad (channels 4sub..4sub+3)

    const uint2* __restrict__ gb = reinterpret_cast<const uint2*>(g_dect2) + sub;

    int P  = (N + 3) >> 2;               // number of j-quads
    int nw = gridDim.x * 16;

    for (int p = blockIdx.x * 16 + wid; p < P; p += nw) {
        int j  = 4 * p + jj;
        int jm = min(j, N - 1);

        // coalesced row loads: 8 lanes x float4/int4 = 128B per point
        float4 dp = nd4[(unsigned)jm * 8u + sub];
        int4   ip = nid4[(unsigned)jm * 8u + sub];

        __syncwarp();
        *reinterpret_cast<float4*>(&d2_sm[wid][jj][4 * sub]) =
            make_float4(dp.x * dp.x, dp.y * dp.y, dp.z * dp.z, dp.w * dp.w);
        *reinterpret_cast<int4*>(&id_sm[wid][jj][4 * sub]) = ip;
        __syncwarp();

        int lab = labels[jm];
        float4 av = *reinterpret_cast<const float4*>(&a_s[lab][4 * sub]);

        // ---- prologue: issue gathers for k = 0..3 (kp = 0,1) ----
        uint2 vh[2][2];
        {
            int4 id03 = *reinterpret_cast<const int4*>(&id_sm[wid][jj][0]);
            vh[0][0] = gb[(unsigned)id03.x * 8u];
            vh[0][1] = gb[(unsigned)id03.y * 8u];
            vh[1][0] = gb[(unsigned)id03.z * 8u];
            vh[1][1] = gb[(unsigned)id03.w * 8u];
        }

        float acc0 = 0.0f, acc1 = 0.0f, acc2 = 0.0f, acc3 = 0.0f;
        #pragma unroll
        for (int kp = 0; kp < 16; kp++) {
            uint2 u0 = vh[kp & 1][0];     // row for k = 2kp   (4 halves)
            uint2 u1 = vh[kp & 1][1];     // row for k = 2kp+1

            if (kp + 2 < 16) {            // re-issue freed slot for kp+2
                int2 idn = *reinterpret_cast<const int2*>(&id_sm[wid][jj][2 * (kp + 2)]);
                vh[kp & 1][0] = gb[(unsigned)idn.x * 8u];
                vh[kp & 1][1] = gb[(unsigned)idn.y * 8u];
            }

            float2 d2  = *reinterpret_cast<const float2*>(&d2_sm[wid][jj][2 * kp]);
            float4 iv0 = *reinterpret_cast<const float4*>(&ivs_s[2 * kp][sub][0]);
            float4 iv1 = *reinterpret_cast<const float4*>(&ivs_s[2 * kp + 1][sub][0]);

            // k = 2kp
            {
                float2 va = __half22float2(*reinterpret_cast<__half2*>(&u0.x));
                float2 vb = __half22float2(*reinterpret_cast<__half2*>(&u0.y));
                float w0 = fmaxf(fmaf(-d2.x, av.x, 1.0f), 0.0f);
                float w1 = fmaxf(fmaf(-d2.x, av.y, 1.0f), 0.0f);
                float w2 = fmaxf(fmaf(-d2.x, av.z, 1.0f), 0.0f);
                float w3 = fmaxf(fmaf(-d2.x, av.w, 1.0f), 0.0f);
                acc0 = fmaf(va.x * w0, iv0.x, acc0);
                acc1 = fmaf(va.y * w1, iv0.y, acc1);
                acc2 = fmaf(vb.x * w2, iv0.z, acc2);
                acc3 = fmaf(vb.y * w3, iv0.w, acc3);
            }
            // k = 2kp+1
            {
                float2 va = __half22float2(*reinterpret_cast<__half2*>(&u1.x));
                float2 vb = __half22float2(*reinterpret_cast<__half2*>(&u1.y));
                float w0 = fmaxf(fmaf(-d2.y, av.x, 1.0f), 0.0f);
                float w1 = fmaxf(fmaf(-d2.y, av.y, 1.0f), 0.0f);
                float w2 = fmaxf(fmaf(-d2.y, av.z, 1.0f), 0.0f);
                float w3 = fmaxf(fmaf(-d2.y, av.w, 1.0f), 0.0f);
                acc0 = fmaf(va.x * w0, iv1.x, acc0);
                acc1 = fmaf(va.y * w1, iv1.y, acc1);
                acc2 = fmaf(vb.x * w2, iv1.z, acc2);
                acc3 = fmaf(vb.y * w3, iv1.w, acc3);
            }
        }

        float s = (acc0 + acc1) + (acc2 + acc3);
        #pragma unroll
        for (int o = 1; o < 8; o <<= 1)
            s += __shfl_xor_sync(0xffffffffu, s, o);   // reduce over 8 lanes of group

        if (sub == 0 && j < N) out[j] = s;
    }
}

// ------------------------------------------------------------------
extern "C" void kernel_launch(void* const* d_in, const int* in_sizes, int n_in,
                              void* d_out, int out_size) {
    const float* x       = (const float*)d_in[0];
    const float* enc_w   = (const float*)d_in[1];
    const float* enc_b   = (const float*)d_in[2];
    const float* decoder = (const float*)d_in[3];
    const float* bw_w    = (const float*)d_in[4];
    const float* bw_b    = (const float*)d_in[5];
    const float* nd      = (const float*)d_in[6];
    const int*   nid     = (const int*)d_in[7];
    const int*   labels  = (const int*)d_in[8];
    float* out = (float*)d_out;
    int N = in_sizes[0];

    kA_encoded<<<dim3(16, NCH), 256>>>(enc_w, x, N);
    kB_bandwidths<<<1, NCH * MCL>>>(bw_w, bw_b, enc_b);
    kT_transpose<<<(N + 255) / 256, 256>>>(decoder, N);
    kPB_sums<<<PB_BLOCKS, 512>>>(nd, labels, N);
    kPF_finalize<<<8, 128>>>(PB_BLOCKS);
    kPC_output<<<296, 512>>>((const float4*)nd, (const int4*)nid, labels, out, N);
}